// round 17
// baseline (speedup 1.0000x reference)
#include <cuda_runtime.h>
#include <math.h>

// Problem constants
#define B_   2
#define C_   512
#define HW_  32768          // H*W = 128*256
#define K_   19
#define GC_  4              // channels per block (1 per warp)
#define NCT_ (C_/GC_)       // 128 channel tiles
#define NCHUNK_ 8
#define PXC_ (HW_/NCHUNK_)  // 4096 pixels per chunk
#define NIT_ (PXC_/128)     // 32 iterations per block
#define NPAIR_ (K_*K_)      // 361
#define NW_    (B_*2*NPAIR_)        // 1444 gram warps
#define GRAMB_ ((NW_ + 7)/8)        // 181 blocks of 8 warps

// Scratch (no cudaMalloc allowed).
// d_cen zero at load; seg accumulates atomically; gram's last block re-zeroes.
__device__ float d_cen[B_*2*C_*K_];
__device__ float d_dots[B_*2*NPAIR_];
__device__ unsigned int d_ctr;

// One S/T float4 pair routed into per-warp float2 bins (bank == f(lane): conflict-free)
#define RMW_(sv, tv, lv)                                                        \
    do {                                                                        \
        float2 v_;                                                              \
        v_ = bin[(lv).x*32 + lane]; v_.x += (sv).x; v_.y += (tv).x; bin[(lv).x*32 + lane] = v_; \
        v_ = bin[(lv).y*32 + lane]; v_.x += (sv).y; v_.y += (tv).y; bin[(lv).y*32 + lane] = v_; \
        v_ = bin[(lv).z*32 + lane]; v_.x += (sv).z; v_.y += (tv).z; bin[(lv).z*32 + lane] = v_; \
        v_ = bin[(lv).w*32 + lane]; v_.x += (sv).w; v_.y += (tv).w; bin[(lv).w*32 + lane] = v_; \
    } while (0)

// ---------------------------------------------------------------------------
// Kernel 1: segment sums. Same code as the 42us R11/R16 version; only the
// min-blocks hint rises 6 -> 7 (current allocation is exactly 72 regs =
// the 7-block budget, so the schedule should be unchanged while resident
// warps go 24 -> 28).
// ---------------------------------------------------------------------------
__global__ __launch_bounds__(128, 7) void seg_kernel(
    const float* __restrict__ S,
    const float* __restrict__ T,
    const int*   __restrict__ tgt)
{
    __shared__ float2 bins[GC_][K_*32];   // 4 warps x 19x32 float2 = 19.5 KB
    __shared__ float  outb[GC_][2][K_];

    int tid  = threadIdx.x;
    int lane = tid & 31;
    int warp = tid >> 5;

    int blk   = blockIdx.x;               // b*1024 + chunk*128 + ct
    int ct    = blk & (NCT_ - 1);
    int chunk = (blk >> 7) & (NCHUNK_ - 1);
    int b     = blk >> 10;
    int c     = ct * GC_ + warp;

    const float4* Sp = (const float4*)(S + ((size_t)(b*C_ + c))*HW_ + chunk*PXC_);
    const float4* Tp = (const float4*)(T + ((size_t)(b*C_ + c))*HW_ + chunk*PXC_);
    const int4*   Lp = (const int4*)(tgt + (size_t)b*HW_ + chunk*PXC_);

    float2* bin = bins[warp];
    for (int i = lane; i < K_*32; i += 32) bin[i] = make_float2(0.f, 0.f);
    __syncwarp();

    // Depth-2 software pipeline.
    float4 s0 = __ldcs(Sp + lane);
    float4 t0 = __ldcs(Tp + lane);
    int4   l0 = __ldg (Lp + lane);
    float4 s1 = __ldcs(Sp + 32 + lane);
    float4 t1 = __ldcs(Tp + 32 + lane);
    int4   l1 = __ldg (Lp + 32 + lane);

#pragma unroll 2
    for (int it = 2; it < NIT_; ++it) {
        int idx = it*32 + lane;
        float4 s2 = __ldcs(Sp + idx);
        float4 t2 = __ldcs(Tp + idx);
        int4   l2 = __ldg (Lp + idx);
        RMW_(s0, t0, l0);
        s0 = s1; t0 = t1; l0 = l1;
        s1 = s2; t1 = t2; l1 = l2;
    }
    RMW_(s0, t0, l0);
    RMW_(s1, t1, l1);
    __syncwarp();

    // Reduce 32 lanes per class; shuffle tree.
#pragma unroll
    for (int k = 0; k < K_; ++k) {
        float2 v = bin[k*32 + lane];
#pragma unroll
        for (int off = 16; off; off >>= 1) {
            v.x += __shfl_down_sync(0xffffffff, v.x, off);
            v.y += __shfl_down_sync(0xffffffff, v.y, off);
        }
        if (lane == 0) { outb[warp][0][k] = v.x; outb[warp][1][k] = v.y; }
    }
    __syncwarp();

    // Accumulate straight into d_cen[(b*2+t)*C*K + c*K + k].
    for (int i = lane; i < 2*K_; i += 32) {   // 38 outputs > 32 lanes: loop
        int t = i >= K_;
        int k = i - t*K_;
        atomicAdd(&d_cen[((size_t)(b*2 + t)*C_ + c)*K_ + k], outb[warp][t][k]);
    }
}

// ---------------------------------------------------------------------------
// Kernel 2: Gram + loss. Warp-per-(bt,i,j) across 181 blocks (L1/L2-hot
// d_cen, each line reused ~19x). Cosine is count-scale-invariant: raw sums.
// Last-arriving block (counter) computes the 722-entry loss, zeroes d_cen
// for the next graph replay (all readers done), and resets the counter.
// ---------------------------------------------------------------------------
__global__ __launch_bounds__(256) void gram_loss_kernel(float* __restrict__ out)
{
    __shared__ float red[8];
    __shared__ int   slast;

    int tid  = threadIdx.x;
    int lane = tid & 31;
    int warp = tid >> 5;
    int gw   = (blockIdx.x*256 + tid) >> 5;   // global warp id

    if (gw < NW_) {
        int bt = gw / NPAIR_;
        int p  = gw - bt*NPAIR_;
        int i  = p / K_, j = p % K_;

        const float* cen = d_cen + (size_t)bt*C_*K_;
        float acc = 0.f;
#pragma unroll
        for (int m = 0; m < C_/32; ++m) {
            int c = m*32 + lane;
            acc += __ldg(cen + c*K_ + i) * __ldg(cen + c*K_ + j);
        }
#pragma unroll
        for (int off = 16; off; off >>= 1)
            acc += __shfl_down_sync(0xffffffff, acc, off);
        if (lane == 0) d_dots[(size_t)bt*NPAIR_ + p] = acc;
    }

    // Arrival (threadFenceReduction pattern: tid0-only release fence).
    __syncthreads();
    if (tid == 0) {
        __threadfence();
        slast = ((int)atomicAdd(&d_ctr, 1u) == GRAMB_ - 1);
    }
    __syncthreads();
    if (!slast) return;
    if (tid == 0) __threadfence();   // acquire all d_dots
    __syncthreads();

    // Loss over 722 (b,i,j) entries.
    float v = 0.f;
    for (int p = tid; p < B_*NPAIR_; p += 256) {
        int j = p % K_; int r = p / K_;
        int i = r % K_; int bb = r / K_;
        const float* dS = d_dots + (size_t)(bb*2 + 0)*NPAIR_;
        const float* dT = d_dots + (size_t)(bb*2 + 1)*NPAIR_;
        float nSi = fmaxf(sqrtf(dS[i*K_ + i]), 1e-8f);
        float nSj = fmaxf(sqrtf(dS[j*K_ + j]), 1e-8f);
        float pS  = dS[i*K_ + j] / (nSi * nSj);
        float nTi = fmaxf(sqrtf(dT[i*K_ + i]), 1e-8f);
        float nTj = fmaxf(sqrtf(dT[j*K_ + j]), 1e-8f);
        float pT  = dT[i*K_ + j] / (nTi * nTj);
        float df  = pS - pT;
        v += df * df;
    }

    // Re-zero accumulator (all gram readers are done: counter full).
    for (int idx = tid; idx < B_*2*C_*K_; idx += 256)
        d_cen[idx] = 0.f;

#pragma unroll
    for (int off = 16; off; off >>= 1)
        v += __shfl_down_sync(0xffffffff, v, off);
    if (lane == 0) red[warp] = v;
    __syncthreads();
    if (tid == 0) {
        float s = 0.f;
#pragma unroll
        for (int w = 0; w < 8; ++w) s += red[w];
        out[0] = s / (float)(B_*NPAIR_);
        d_ctr  = 0;                   // reset for next graph replay
    }
}

// ---------------------------------------------------------------------------
extern "C" void kernel_launch(void* const* d_in, const int* in_sizes, int n_in,
                              void* d_out, int out_size)
{
    const float* S   = (const float*)d_in[0];   // preds_S [2,512,128,256] f32
    const float* T   = (const float*)d_in[1];   // preds_T [2,512,128,256] f32
    const int*   tgt = (const int*)  d_in[2];   // target  [2,1,128,256] i32
    float* out = (float*)d_out;                 // scalar f32

    seg_kernel<<<B_*NCT_*NCHUNK_, 128>>>(S, T, tgt);   // 2048 blocks
    gram_loss_kernel<<<GRAMB_, 256>>>(out);            // 181 blocks
}